// round 11
// baseline (speedup 1.0000x reference)
#include <cuda_runtime.h>
#include <math.h>

// Problem constants
#define B     32
#define C     512
#define HW    3136          // 56*56
#define HW4   784           // HW / 4 (float4)
#define HID   32            // C / RED
#define KSEL  256           // C / 2
#define NROW  (B * C)       // 16384 rows

// Chunked pipeline
#define CHUNK_B   8                 // batches per chunk (51.4 MB)
#define NCHUNK    (B / CHUNK_B)     // 4
#define CH_ROWS   (CHUNK_B * C)     // 4096 rows
#define POOL_CTAS 512               // 8 warps/CTA -> 4096 rows
#define SCALE_CTAS 512

// Allocation-free scratch
__device__ float g_y[NROW];      // pooled mean+max per (b,c)
__device__ float g_map[NROW];    // final per-channel multiplier
__device__ unsigned g_done = 0;  // pool-CTA completion counter (self-resetting)

// ---------------------------------------------------------------------------
// Fused pipeline step:
//   blocks [0, pool_ctas)              : pool rows of chunk `pool_ch`
//       (the LAST pool CTA to finish also runs the MLP+mask for that chunk)
//   blocks [pool_ctas, pool_ctas+512)  : scale rows of chunk `scale_ch`
// Stream order between launches provides pool->scale dependency across chunks.
// ---------------------------------------------------------------------------
__global__ __launch_bounds__(256) void step_kernel(
    const float* __restrict__ x, float* __restrict__ out,
    const float* __restrict__ w1, const float* __restrict__ b1,
    const float* __restrict__ prelu_a,
    const float* __restrict__ w2, const float* __restrict__ b2,
    const float* __restrict__ rand,
    int pool_ch, int scale_ch, int pool_ctas)
{
    const int t   = threadIdx.x;
    const int wid = t >> 5;
    const int lid = t & 31;

    // All shared state at kernel scope, 16B-aligned (y2_s/y_s are read via
    // float4* -> LDS.128 requires 16-byte alignment; this was the round-8 trap).
    __shared__ __align__(16) float y_s[C];
    __shared__ __align__(16) float y2_s[C];
    __shared__ __align__(16) float hpart[8][HID];
    __shared__ __align__(16) float h_s[HID];
    __shared__ int is_last;

    if ((int)blockIdx.x < pool_ctas) {
        // ========================= POOL part ==============================
        const int row = pool_ch * CH_ROWS + blockIdx.x * 8 + wid;
        {
            const float4* __restrict__ r =
                reinterpret_cast<const float4*>(x + (size_t)row * HW);
            float s = 0.0f;
            float m = -INFINITY;
            int i = lid;
            #pragma unroll 1
            for (; i + 96 < HW4; i += 128) {
                float4 a = r[i];
                float4 b = r[i + 32];
                float4 c = r[i + 64];
                float4 d = r[i + 96];
                s += (a.x + a.y) + (a.z + a.w);
                s += (b.x + b.y) + (b.z + b.w);
                s += (c.x + c.y) + (c.z + c.w);
                s += (d.x + d.y) + (d.z + d.w);
                m = fmaxf(m, fmaxf(fmaxf(a.x, a.y), fmaxf(a.z, a.w)));
                m = fmaxf(m, fmaxf(fmaxf(b.x, b.y), fmaxf(b.z, b.w)));
                m = fmaxf(m, fmaxf(fmaxf(c.x, c.y), fmaxf(c.z, c.w)));
                m = fmaxf(m, fmaxf(fmaxf(d.x, d.y), fmaxf(d.z, d.w)));
            }
            for (; i < HW4; i += 32) {
                float4 a = r[i];
                s += (a.x + a.y) + (a.z + a.w);
                m = fmaxf(m, fmaxf(fmaxf(a.x, a.y), fmaxf(a.z, a.w)));
            }
            #pragma unroll
            for (int off = 16; off > 0; off >>= 1) {
                s += __shfl_xor_sync(0xFFFFFFFFu, s, off);
                m = fmaxf(m, __shfl_xor_sync(0xFFFFFFFFu, m, off));
            }
            if (lid == 0)
                g_y[row] = s * (1.0f / (float)HW) + m;
        }

        // -------- last-CTA detection (fence + atomic, no grid barrier) -----
        __threadfence();                       // publish g_y writes
        __syncthreads();
        if (t == 0) {
            unsigned n = atomicAdd(&g_done, 1u);
            is_last = (n == (unsigned)(pool_ctas - 1));
            if (is_last) atomicExch(&g_done, 0u);   // reset for next launch
        }
        __syncthreads();

        if (is_last) {
            // ============ MLP + sigmoid + rank mask for 8 batches ==========
            for (int bb = 0; bb < CHUNK_B; bb++) {
                const int b = pool_ch * CHUNK_B + bb;

                y_s[t]       = __ldcg(&g_y[b * C + t]);
                y_s[t + 256] = __ldcg(&g_y[b * C + t + 256]);
                __syncthreads();

                // h partials: warp w covers channels [64w,64w+64), lane = hid j
                {
                    float acc = 0.0f;
                    const int c0 = wid * 64;
                    #pragma unroll
                    for (int k = 0; k < 64; k++)
                        acc = fmaf(y_s[c0 + k], __ldg(&w1[(c0 + k) * HID + lid]), acc);
                    hpart[wid][lid] = acc;
                }
                __syncthreads();

                if (t < HID) {
                    float acc = b1[t];
                    #pragma unroll
                    for (int w = 0; w < 8; w++) acc += hpart[w][t];
                    const float a = prelu_a[0];
                    h_s[t] = (acc >= 0.0f) ? acc : a * acc;
                }
                __syncthreads();

                float acc0 = __ldg(&b2[t]);
                float acc1 = __ldg(&b2[t + 256]);
                #pragma unroll
                for (int j = 0; j < HID; j++) {
                    const float hj = h_s[j];
                    acc0 = fmaf(hj, __ldg(&w2[j * C + t]),       acc0);
                    acc1 = fmaf(hj, __ldg(&w2[j * C + t + 256]), acc1);
                }
                const float v0 = 1.0f / (1.0f + expf(-acc0));
                const float v1 = 1.0f / (1.0f + expf(-acc1));
                y2_s[t]       = v0;
                y2_s[t + 256] = v1;
                __syncthreads();

                // rank count: mask_c = (#{i: y2_i > y2_c} >= K)
                int g0 = 0, g1 = 0;
                const float4* __restrict__ yv =
                    reinterpret_cast<const float4*>(y2_s);
                #pragma unroll 4
                for (int i = 0; i < C / 4; i++) {
                    float4 q = yv[i];
                    g0 += (q.x > v0) + (q.y > v0) + (q.z > v0) + (q.w > v0);
                    g1 += (q.x > v1) + (q.y > v1) + (q.z > v1) + (q.w > v1);
                }
                const bool bel0 = (g0 >= KSEL);
                const bool bel1 = (g1 >= KSEL);
                const bool rb0 = (__ldg(&rand[b * C + t])       - 0.5f < 0.0f);
                const bool rb1 = (__ldg(&rand[b * C + t + 256]) - 0.5f < 0.0f);
                g_map[b * C + t]       = rb0 ? (bel0 ? v0 : 0.0f) : v0;
                g_map[b * C + t + 256] = rb1 ? (bel1 ? v1 : 0.0f) : v1;
                __syncthreads();
            }
        }
    } else if (scale_ch >= 0) {
        // ========================= SCALE part =============================
        const int cta2 = blockIdx.x - pool_ctas;
        const int row  = scale_ch * CH_ROWS + cta2 * 8 + wid;
        const float f  = g_map[row];
        float4* __restrict__ oo =
            reinterpret_cast<float4*>(out + (size_t)row * HW);

        if (f == 0.0f) {
            const float4 z = make_float4(0.0f, 0.0f, 0.0f, 0.0f);
            for (int i = lid; i < HW4; i += 32)
                __stcs(&oo[i], z);
        } else {
            const float4* __restrict__ xi =
                reinterpret_cast<const float4*>(x + (size_t)row * HW);
            int i = lid;
            #pragma unroll 1
            for (; i + 96 < HW4; i += 128) {
                float4 a = __ldcs(&xi[i]);
                float4 b = __ldcs(&xi[i + 32]);
                float4 c = __ldcs(&xi[i + 64]);
                float4 d = __ldcs(&xi[i + 96]);
                a.x *= f; a.y *= f; a.z *= f; a.w *= f;
                b.x *= f; b.y *= f; b.z *= f; b.w *= f;
                c.x *= f; c.y *= f; c.z *= f; c.w *= f;
                d.x *= f; d.y *= f; d.z *= f; d.w *= f;
                __stcs(&oo[i],      a);
                __stcs(&oo[i + 32], b);
                __stcs(&oo[i + 64], c);
                __stcs(&oo[i + 96], d);
            }
            for (; i < HW4; i += 32) {
                float4 a = __ldcs(&xi[i]);
                a.x *= f; a.y *= f; a.z *= f; a.w *= f;
                __stcs(&oo[i], a);
            }
        }
    }
}

// ---------------------------------------------------------------------------
// Launch: 5 graph-ordered steps.
//   K0: pool(0)                K1: pool(1)+scale(0)   K2: pool(2)+scale(1)
//   K3: pool(3)+scale(2)       K4: scale(3)
// ---------------------------------------------------------------------------
extern "C" void kernel_launch(void* const* d_in, const int* in_sizes, int n_in,
                              void* d_out, int out_size) {
    const float* x       = (const float*)d_in[0];
    const float* w1      = (const float*)d_in[1];
    const float* b1      = (const float*)d_in[2];
    const float* prelu_a = (const float*)d_in[3];
    const float* w2      = (const float*)d_in[4];
    const float* b2      = (const float*)d_in[5];
    const float* rand    = (const float*)d_in[6];
    float* out = (float*)d_out;

    // K0: pool only
    step_kernel<<<POOL_CTAS, 256>>>(x, out, w1, b1, prelu_a, w2, b2, rand,
                                    0, -1, POOL_CTAS);
    // K1..K3: pool(ch) + scale(ch-1)
    for (int ch = 1; ch < NCHUNK; ch++) {
        step_kernel<<<POOL_CTAS + SCALE_CTAS, 256>>>(
            x, out, w1, b1, prelu_a, w2, b2, rand, ch, ch - 1, POOL_CTAS);
    }
    // K4: scale only
    step_kernel<<<SCALE_CTAS, 256>>>(x, out, w1, b1, prelu_a, w2, b2, rand,
                                     -1, NCHUNK - 1, 0);
}

// round 14
// speedup vs baseline: 3.9487x; 3.9487x over previous
#include <cuda_runtime.h>
#include <math.h>

// Problem constants
#define B   32
#define C   512
#define HW  3136          // 56*56
#define HW4 784           // HW / 4 (float4)
#define HID 32            // C / RED
#define KSEL 256          // C / 2
#define NROW (B * C)      // 16384 rows

// Allocation-free scratch (device globals)
__device__ float g_y[NROW];     // pooled mean+max per (b,c)
__device__ float g_map[NROW];   // final per-channel multiplier

// Force a v4 load that ptxas cannot sink/reorder past the batch.
__device__ __forceinline__ float4 ldg_v4(const float4* p) {
    float4 v;
    asm volatile("ld.global.nc.v4.f32 {%0,%1,%2,%3}, [%4];"
                 : "=f"(v.x), "=f"(v.y), "=f"(v.z), "=f"(v.w) : "l"(p));
    return v;
}

// ---------------------------------------------------------------------------
// Kernel 1: per-(b,c) mean + max over 3136 spatial elements.
// One WARP per row. 8 loads issued back-to-back via inline asm (true MLP=8).
// ---------------------------------------------------------------------------
__global__ __launch_bounds__(256) void pool_kernel(const float* __restrict__ x) {
    const int row = blockIdx.x * 8 + (threadIdx.x >> 5);
    const int lid = threadIdx.x & 31;
    const float4* __restrict__ r =
        reinterpret_cast<const float4*>(x + (size_t)row * HW);

    float s = 0.0f;
    float m = -INFINITY;

    // 784 = 3*256 + 16 : 3 iterations of 8 batched loads, 16-lane tail
    int i = lid;
    #pragma unroll 1
    for (; i + 224 < HW4; i += 256) {
        // Batch of 8 independent loads — issued before any consumption.
        float4 v0 = ldg_v4(r + i);
        float4 v1 = ldg_v4(r + i + 32);
        float4 v2 = ldg_v4(r + i + 64);
        float4 v3 = ldg_v4(r + i + 96);
        float4 v4 = ldg_v4(r + i + 128);
        float4 v5 = ldg_v4(r + i + 160);
        float4 v6 = ldg_v4(r + i + 192);
        float4 v7 = ldg_v4(r + i + 224);
        s += (v0.x + v0.y) + (v0.z + v0.w);
        s += (v1.x + v1.y) + (v1.z + v1.w);
        s += (v2.x + v2.y) + (v2.z + v2.w);
        s += (v3.x + v3.y) + (v3.z + v3.w);
        s += (v4.x + v4.y) + (v4.z + v4.w);
        s += (v5.x + v5.y) + (v5.z + v5.w);
        s += (v6.x + v6.y) + (v6.z + v6.w);
        s += (v7.x + v7.y) + (v7.z + v7.w);
        m = fmaxf(m, fmaxf(fmaxf(v0.x, v0.y), fmaxf(v0.z, v0.w)));
        m = fmaxf(m, fmaxf(fmaxf(v1.x, v1.y), fmaxf(v1.z, v1.w)));
        m = fmaxf(m, fmaxf(fmaxf(v2.x, v2.y), fmaxf(v2.z, v2.w)));
        m = fmaxf(m, fmaxf(fmaxf(v3.x, v3.y), fmaxf(v3.z, v3.w)));
        m = fmaxf(m, fmaxf(fmaxf(v4.x, v4.y), fmaxf(v4.z, v4.w)));
        m = fmaxf(m, fmaxf(fmaxf(v5.x, v5.y), fmaxf(v5.z, v5.w)));
        m = fmaxf(m, fmaxf(fmaxf(v6.x, v6.y), fmaxf(v6.z, v6.w)));
        m = fmaxf(m, fmaxf(fmaxf(v7.x, v7.y), fmaxf(v7.z, v7.w)));
    }
    if (i < HW4) {   // tail: lanes 0..15, one load each
        float4 a = ldg_v4(r + i);
        s += (a.x + a.y) + (a.z + a.w);
        m = fmaxf(m, fmaxf(fmaxf(a.x, a.y), fmaxf(a.z, a.w)));
    }

    // warp reduce
    #pragma unroll
    for (int off = 16; off > 0; off >>= 1) {
        s += __shfl_xor_sync(0xFFFFFFFFu, s, off);
        m = fmaxf(m, __shfl_xor_sync(0xFFFFFFFFu, m, off));
    }
    if (lid == 0)
        g_y[row] = s * (1.0f / (float)HW) + m;
}

// ---------------------------------------------------------------------------
// Kernel 2: tiny MLP + sigmoid + rank-mask + rand gate.
// One block per batch, 512 threads (one per channel).
// mask_t = (#{i : y2_i > y2_t} >= K)  <=>  y2_t < min(top_K)  (tie-correct)
// ---------------------------------------------------------------------------
__global__ __launch_bounds__(512) void mlp_mask_kernel(
    const float* __restrict__ w1, const float* __restrict__ b1,
    const float* __restrict__ prelu_a,
    const float* __restrict__ w2, const float* __restrict__ b2,
    const float* __restrict__ rand)
{
    const int b = blockIdx.x;
    const int t = threadIdx.x;
    const int wid = t >> 5;     // warp 0..15
    const int lid = t & 31;

    __shared__ __align__(16) float y_s[C];
    __shared__ __align__(16) float hpart[16][HID];
    __shared__ __align__(16) float h_s[HID];
    __shared__ __align__(16) float y2_s[C];

    y_s[t] = g_y[b * C + t];
    __syncthreads();

    // h partials: warp w covers channels [32w, 32w+32), lane j = hidden unit j.
    {
        float acc = 0.0f;
        const int c0 = wid * 32;
        #pragma unroll
        for (int k = 0; k < 32; k++) {
            const int c = c0 + k;
            acc = fmaf(y_s[c], __ldg(&w1[c * HID + lid]), acc);
        }
        hpart[wid][lid] = acc;
    }
    __syncthreads();

    // reduce the 16 partials + bias + PReLU (threads 0..31)
    if (t < HID) {
        float acc = b1[t];
        #pragma unroll
        for (int w = 0; w < 16; w++) acc += hpart[w][t];
        const float a = prelu_a[0];
        h_s[t] = (acc >= 0.0f) ? acc : a * acc;
    }
    __syncthreads();

    // y2[t] = sigmoid(h @ w2 + b2)
    float acc = __ldg(&b2[t]);
    #pragma unroll
    for (int j = 0; j < HID; j++)
        acc = fmaf(h_s[j], __ldg(&w2[j * C + t]), acc);
    const float y2 = 1.0f / (1.0f + expf(-acc));
    y2_s[t] = y2;
    __syncthreads();

    // rank count: number of strictly-greater elements (vectorized smem scan)
    int g = 0;
    const float4* __restrict__ yv = reinterpret_cast<const float4*>(y2_s);
    #pragma unroll 4
    for (int i = 0; i < C / 4; i++) {
        float4 q = yv[i];
        g += (q.x > y2) + (q.y > y2) + (q.z > y2) + (q.w > y2);
    }

    const bool below = (g >= KSEL);                    // y2 < k-th largest
    const bool rb = (__ldg(&rand[b * C + t]) - 0.5f < 0.0f);
    // final_map = rb ? (mask * y2) : y2
    const float fm = rb ? (below ? y2 : 0.0f) : y2;
    g_map[b * C + t] = fm;
}

// ---------------------------------------------------------------------------
// Kernel 3: out = x * final_map (broadcast over spatial).
// Reversed row order (L2 tail reuse from pool), streaming ld/st.
// ZERO-SKIP: final_map == 0 iff masked&gated (~25% of rows, sigmoid > 0
// always) -> skip the x read entirely, stream zeros.
// ---------------------------------------------------------------------------
__global__ __launch_bounds__(256) void scale_kernel(
    const float* __restrict__ x, float* __restrict__ out)
{
    const int bc = (NROW - 1) - blockIdx.x;   // reversed
    const float f = g_map[bc];
    float4* __restrict__ oo =
        reinterpret_cast<float4*>(out + (size_t)bc * HW);

    if (f == 0.0f) {
        const float4 z = make_float4(0.0f, 0.0f, 0.0f, 0.0f);
        for (int i = threadIdx.x; i < HW4; i += 256)
            __stcs(&oo[i], z);
        return;
    }

    const float4* __restrict__ xi =
        reinterpret_cast<const float4*>(x + (size_t)bc * HW);

    int i = threadIdx.x;
    // 784 = 3*256 + 16: 3 full iterations + tail
    #pragma unroll 1
    for (; i + 512 < HW4; i += 768) {
        float4 a = __ldcs(&xi[i]);
        float4 b = __ldcs(&xi[i + 256]);
        float4 c = __ldcs(&xi[i + 512]);
        a.x *= f; a.y *= f; a.z *= f; a.w *= f;
        b.x *= f; b.y *= f; b.z *= f; b.w *= f;
        c.x *= f; c.y *= f; c.z *= f; c.w *= f;
        __stcs(&oo[i], a);
        __stcs(&oo[i + 256], b);
        __stcs(&oo[i + 512], c);
    }
    for (; i < HW4; i += 256) {
        float4 a = __ldcs(&xi[i]);
        a.x *= f; a.y *= f; a.z *= f; a.w *= f;
        __stcs(&oo[i], a);
    }
}

// ---------------------------------------------------------------------------
// Launch. Inputs (metadata order): x, w1, b1, prelu_a, w2, b2, rand
// ---------------------------------------------------------------------------
extern "C" void kernel_launch(void* const* d_in, const int* in_sizes, int n_in,
                              void* d_out, int out_size) {
    const float* x       = (const float*)d_in[0];
    const float* w1      = (const float*)d_in[1];
    const float* b1      = (const float*)d_in[2];
    const float* prelu_a = (const float*)d_in[3];
    const float* w2      = (const float*)d_in[4];
    const float* b2      = (const float*)d_in[5];
    const float* rand    = (const float*)d_in[6];
    float* out = (float*)d_out;

    pool_kernel<<<NROW / 8, 256>>>(x);
    mlp_mask_kernel<<<B, C>>>(w1, b1, prelu_a, w2, b2, rand);
    scale_kernel<<<NROW, 256>>>(x, out);
}